// round 3
// baseline (speedup 1.0000x reference)
#include <cuda_runtime.h>
#include <cuda_bf16.h>

#define B_  256
#define K_  500
#define H_  152
#define W_  272
#define HW_ (H_ * W_)
#define HASH_SIZE 1024
#define NTHREADS 1024         // 2 batch elements per block, 512 threads each
#define NBLOCKS  (B_ / 2)     // 128 blocks -> single wave on 148 SMs
#define ID_MASK  ((1 << 18) - 1)

__device__ float    g_pnum[NBLOCKS];
__device__ float    g_pmask[NBLOCKS];
__device__ unsigned g_count = 0;

__device__ __forceinline__ unsigned hash_id(int id) {
    return ((unsigned)id * 2654435761u) & (HASH_SIZE - 1);
}

__global__ __launch_bounds__(NTHREADS) void fwd_loss_fused(
    const float* __restrict__ flow,   // [B,2,H,W]
    const float* __restrict__ mask,   // [B,K]
    const int*   __restrict__ index,  // [B,K]
    const int*   __restrict__ ids,    // [B,K]
    const int*   __restrict__ index2, // [B,K]
    const int*   __restrict__ ids2,   // [B,K]
    float*       __restrict__ out)
{
    __shared__ int    hpack[2][HASH_SIZE];    // (k<<18)|id ; 0 = empty
    __shared__ float2 sxy[2][K_];             // flow*mask per position k
    __shared__ float  red_num[NTHREADS / 32];
    __shared__ float  red_msk[NTHREADS / 32];

    const int tid = threadIdx.x;
    const int sel = tid >> 9;          // 0 or 1: which batch half
    const int lb  = tid & 511;         // local index within half
    const int b   = blockIdx.x * 2 + sel;

    // hash init: each half inits its own table
    #pragma unroll
    for (int i = lb; i < HASH_SIZE; i += 512) hpack[sel][i] = 0;

    // ---- Phase A: issue all global loads up front (one latency epoch) ----
    int   id = 0, id2 = 0, i2 = 0;
    float m = 0.0f, px = 0.0f, py = 0.0f;
    if (lb < K_) {
        const int g = b * K_ + lb;
        id  = ids[g];
        m   = mask[g];
        id2 = ids2[g];
        i2  = index2[g];
        if (m != 0.0f) {                       // mask==0 -> px=py=0, skip gather
            int p = index[g];
            const float* fb = flow + (size_t)b * 2 * HW_;
            px = fb[p] * m;
            py = fb[HW_ + p] * m;
        }
    }
    __syncthreads();   // hash tables initialized

    if (lb < K_) {
        sxy[sel][lb] = make_float2(px, py);
        int packed = (lb << 18) | id;          // id in 1..20000, nonzero
        unsigned slot = hash_id(id);
        while (atomicCAS(&hpack[sel][slot], 0, packed) != 0)
            slot = (slot + 1) & (HASH_SIZE - 1);
    }
    __syncthreads();

    // ---- Phase B: probe + accumulate (shared memory only) ----
    float lnum = 0.0f, lmask = m;
    if (lb < K_ && id2 != 0) {
        unsigned slot = hash_id(id2);
        int x = -1;
        while (true) {
            int pk = hpack[sel][slot];
            if (pk == 0) break;                          // absent
            if ((pk & ID_MASK) == id2) { x = pk >> 18; break; }
            slot = (slot + 1) & (HASH_SIZE - 1);
        }
        if (x >= 0) {
            float2 s  = sxy[sel][x];
            float  vx = (float)(i2 % W_);
            float  vy = (float)i2 / (float)W_;
            lnum = fabsf(s.x - vx) + fabsf(s.y - vy);
        }
    }

    // ---- Block reduction (both halves together) ----
    const int lane = tid & 31;
    const int warp = tid >> 5;
    #pragma unroll
    for (int off = 16; off > 0; off >>= 1) {
        lnum  += __shfl_down_sync(0xFFFFFFFFu, lnum,  off);
        lmask += __shfl_down_sync(0xFFFFFFFFu, lmask, off);
    }
    if (lane == 0) { red_num[warp] = lnum; red_msk[warp] = lmask; }
    __syncthreads();

    __shared__ bool s_last;
    if (warp == 0) {
        float n  = red_num[lane];   // 32 warps == 32 lanes exactly
        float mm = red_msk[lane];
        #pragma unroll
        for (int off = 16; off > 0; off >>= 1) {
            n  += __shfl_down_sync(0xFFFFFFFFu, n,  off);
            mm += __shfl_down_sync(0xFFFFFFFFu, mm, off);
        }
        if (lane == 0) {
            g_pnum[blockIdx.x]  = n;
            g_pmask[blockIdx.x] = mm;
            __threadfence();
            unsigned prev = atomicAdd(&g_count, 1u);
            s_last = (prev == NBLOCKS - 1);
        }
    }
    __syncthreads();

    // ---- Last block: final deterministic reduction over 128 partials ----
    if (s_last) {
        __threadfence();
        float n = 0.0f, mm = 0.0f;
        if (tid < NBLOCKS) { n = g_pnum[tid]; mm = g_pmask[tid]; }
        #pragma unroll
        for (int off = 16; off > 0; off >>= 1) {
            n  += __shfl_down_sync(0xFFFFFFFFu, n,  off);
            mm += __shfl_down_sync(0xFFFFFFFFu, mm, off);
        }
        if (lane == 0) { red_num[warp] = n; red_msk[warp] = mm; }
        __syncthreads();
        if (tid == 0) {
            float nn = 0.0f, mt = 0.0f;
            #pragma unroll
            for (int w = 0; w < NBLOCKS / 32; w++) { nn += red_num[w]; mt += red_msk[w]; }
            out[0]  = nn / (2.0f * mt + 0.0001f);
            g_count = 0;   // reset for next graph replay
        }
    }
}

extern "C" void kernel_launch(void* const* d_in, const int* in_sizes, int n_in,
                              void* d_out, int out_size) {
    const float* flow   = (const float*)d_in[0];
    const float* mask   = (const float*)d_in[1];
    const int*   index  = (const int*)  d_in[2];
    const int*   ids    = (const int*)  d_in[3];
    const int*   index2 = (const int*)  d_in[4];
    const int*   ids2   = (const int*)  d_in[5];
    float* out = (float*)d_out;

    fwd_loss_fused<<<NBLOCKS, NTHREADS>>>(flow, mask, index, ids, index2, ids2, out);
}

// round 4
// speedup vs baseline: 1.1575x; 1.1575x over previous
#include <cuda_runtime.h>
#include <cuda_bf16.h>

#define B_  256
#define K_  500
#define H_  152
#define W_  272
#define HW_ (H_ * W_)
#define HASH_SIZE 1024
#define NTHREADS 512
#define NBLOCKS  B_
#define ID_MASK  ((1 << 18) - 1)

__device__ float2   g_part[NBLOCKS];   // (num, mask) per block
__device__ unsigned g_count = 0;

__device__ __forceinline__ unsigned hash_id(int id) {
    return ((unsigned)id * 2654435761u) & (HASH_SIZE - 1);
}

__global__ __launch_bounds__(NTHREADS) void fwd_loss_fused(
    const float* __restrict__ flow,   // [B,2,H,W]
    const float* __restrict__ mask,   // [B,K]
    const int*   __restrict__ index,  // [B,K]
    const int*   __restrict__ ids,    // [B,K]
    const int*   __restrict__ index2, // [B,K]
    const int*   __restrict__ ids2,   // [B,K]
    float*       __restrict__ out)
{
    __shared__ int    hpack[HASH_SIZE];       // (k<<18)|id ; 0 = empty
    __shared__ float2 sxy[K_];                // flow*mask per position k
    __shared__ float  red_num[NTHREADS / 32];
    __shared__ float  red_msk[NTHREADS / 32];

    const int b   = blockIdx.x;
    const int tid = threadIdx.x;

    // hash init (overlaps with the global loads below)
    #pragma unroll
    for (int i = tid; i < HASH_SIZE; i += NTHREADS) hpack[i] = 0;

    // ---- Phase A: issue all global loads up front (one latency epoch) ----
    int   id = 0, id2 = 0, i2 = 0;
    float m = 0.0f, px = 0.0f, py = 0.0f;
    if (tid < K_) {
        const int g = b * K_ + tid;
        id  = __ldg(&ids[g]);
        m   = __ldg(&mask[g]);
        id2 = __ldg(&ids2[g]);
        i2  = __ldg(&index2[g]);
        int p = __ldg(&index[g]);
        if (m != 0.0f) {                       // mask==0 -> px=py=0, skip gather
            const float* fb = flow + (size_t)b * 2 * HW_;
            px = __ldcs(&fb[p]) * m;           // channel 0 (streaming)
            py = __ldcs(&fb[HW_ + p]) * m;     // channel 1
        }
    }
    __syncthreads();   // hash table initialized

    if (tid < K_) {
        sxy[tid] = make_float2(px, py);
        int packed = (tid << 18) | id;         // id in 1..20000, nonzero
        unsigned slot = hash_id(id);
        while (atomicCAS(&hpack[slot], 0, packed) != 0)
            slot = (slot + 1) & (HASH_SIZE - 1);
    }
    __syncthreads();

    // ---- Phase B: probe + accumulate (shared memory only) ----
    float lnum = 0.0f, lmask = m;
    if (tid < K_ && id2 != 0) {
        unsigned slot = hash_id(id2);
        int x = -1;
        while (true) {
            int pk = hpack[slot];
            if (pk == 0) break;                           // absent
            if ((pk & ID_MASK) == id2) { x = pk >> 18; break; }
            slot = (slot + 1) & (HASH_SIZE - 1);
        }
        if (x >= 0) {
            float2 s  = sxy[x];
            float  vx = (float)(i2 % W_);
            float  vy = (float)i2 / (float)W_;
            lnum = fabsf(s.x - vx) + fabsf(s.y - vy);
        }
    }

    // ---- Block reduction ----
    const int lane = tid & 31;
    const int warp = tid >> 5;
    #pragma unroll
    for (int off = 16; off > 0; off >>= 1) {
        lnum  += __shfl_down_sync(0xFFFFFFFFu, lnum,  off);
        lmask += __shfl_down_sync(0xFFFFFFFFu, lmask, off);
    }
    if (lane == 0) { red_num[warp] = lnum; red_msk[warp] = lmask; }
    __syncthreads();

    __shared__ bool s_last;
    if (warp == 0) {
        float n  = (lane < NTHREADS / 32) ? red_num[lane] : 0.0f;
        float mm = (lane < NTHREADS / 32) ? red_msk[lane] : 0.0f;
        #pragma unroll
        for (int off = 8; off > 0; off >>= 1) {
            n  += __shfl_down_sync(0xFFFFFFFFu, n,  off);
            mm += __shfl_down_sync(0xFFFFFFFFu, mm, off);
        }
        if (lane == 0) {
            g_part[b] = make_float2(n, mm);
            __threadfence();
            unsigned prev = atomicAdd(&g_count, 1u);
            s_last = (prev == NBLOCKS - 1);
        }
    }
    __syncthreads();

    // ---- Last block: deterministic final reduction over 256 partials ----
    if (s_last) {
        __threadfence();
        float n = 0.0f, mm = 0.0f;
        if (tid < NBLOCKS) {
            float2 p2 = g_part[tid];
            n = p2.x; mm = p2.y;
        }
        #pragma unroll
        for (int off = 16; off > 0; off >>= 1) {
            n  += __shfl_down_sync(0xFFFFFFFFu, n,  off);
            mm += __shfl_down_sync(0xFFFFFFFFu, mm, off);
        }
        if (lane == 0) { red_num[warp] = n; red_msk[warp] = mm; }
        __syncthreads();
        if (tid == 0) {
            float nn = 0.0f, mt = 0.0f;
            #pragma unroll
            for (int w = 0; w < NBLOCKS / 32; w++) { nn += red_num[w]; mt += red_msk[w]; }
            out[0]  = nn / (2.0f * mt + 0.0001f);
            g_count = 0;   // reset for next graph replay
        }
    }
}

extern "C" void kernel_launch(void* const* d_in, const int* in_sizes, int n_in,
                              void* d_out, int out_size) {
    const float* flow   = (const float*)d_in[0];
    const float* mask   = (const float*)d_in[1];
    const int*   index  = (const int*)  d_in[2];
    const int*   ids    = (const int*)  d_in[3];
    const int*   index2 = (const int*)  d_in[4];
    const int*   ids2   = (const int*)  d_in[5];
    float* out = (float*)d_out;

    fwd_loss_fused<<<NBLOCKS, NTHREADS>>>(flow, mask, index, ids, index2, ids2, out);
}